// round 16
// baseline (speedup 1.0000x reference)
#include <cuda_runtime.h>
#include <cuda_bf16.h>
#include <cstdint>

#define N_MAX 50000
#define D 128

// ---- scratch (__device__ globals; no cudaMalloc allowed) -------------------
// Invariant maintained across graph replays: g_agg, g_deg_out, g_deg_in are
// ZERO at kernel_launch entry (module-load init for run 1; each run re-zeros
// them after their last read).
__device__ float g_agg[N_MAX * D];     // scatter accumulator [N,128]
__device__ int   g_deg_out[N_MAX];
__device__ int   g_deg_in[N_MAX];
__device__ float g_ns[N_MAX];          // rsqrt(max(deg_out,1))
__device__ float g_nd[N_MAX];          // rsqrt(max(deg_in,1))
__device__ float g_Wfused[D * D];      // W_conv @ W_aggr[0:128]
__device__ float g_bias[D];            // b_conv @ Wa1 + b_aggr

// ---------------------------------------------------------------------------
// K1: degree histograms — 4 edges per thread via int4
__global__ void deg_kernel(const int* __restrict__ src,
                           const int* __restrict__ dst, int E) {
    int t = blockIdx.x * blockDim.x + threadIdx.x;
    int i = t * 4;
    if (i + 3 < E) {
        int4 s = *(const int4*)(src + i);
        int4 d = *(const int4*)(dst + i);
        atomicAdd(&g_deg_out[s.x], 1);
        atomicAdd(&g_deg_out[s.y], 1);
        atomicAdd(&g_deg_out[s.z], 1);
        atomicAdd(&g_deg_out[s.w], 1);
        atomicAdd(&g_deg_in[d.x], 1);
        atomicAdd(&g_deg_in[d.y], 1);
        atomicAdd(&g_deg_in[d.z], 1);
        atomicAdd(&g_deg_in[d.w], 1);
    } else {
        for (int e = i; e < E; e++) {
            atomicAdd(&g_deg_out[src[e]], 1);
            atomicAdd(&g_deg_in[dst[e]], 1);
        }
    }
}

// K2: fused weight prep + norm factors (+ deg re-zero for next replay).
__global__ __launch_bounds__(1024) void fuse_kernel(
    const float* __restrict__ Wc,
    const float* __restrict__ Wa,
    const float* __restrict__ bc,
    const float* __restrict__ ba, int n) {
    int tid = threadIdx.x;
    int b = blockIdx.x;
    if (b > D) {
        int i = (b - D - 1) * 1024 + tid;
        if (i < n) {
            g_ns[i] = rsqrtf(fmaxf((float)__ldg(&g_deg_out[i]), 1.0f));
            g_nd[i] = rsqrtf(fmaxf((float)__ldg(&g_deg_in[i]), 1.0f));
            g_deg_out[i] = 0;          // restore invariant for next replay
            g_deg_in[i] = 0;
        }
        return;
    }
    __shared__ float wc[D];
    __shared__ float part[8][D];
    int j = tid & 127;
    int g = tid >> 7;          // k-group 0..7
    if (tid < D) wc[tid] = (b < D) ? __ldg(&Wc[b * D + tid]) : __ldg(&bc[tid]);
    __syncthreads();

    int k0 = g * 16;
    float a[8];
#pragma unroll
    for (int i = 0; i < 8; i++) a[i] = 0.f;
#pragma unroll
    for (int kk = 0; kk < 16; kk++)
        a[kk & 7] += wc[k0 + kk] * __ldg(&Wa[(k0 + kk) * D + j]);
    part[g][j] = ((a[0] + a[1]) + (a[2] + a[3])) + ((a[4] + a[5]) + (a[6] + a[7]));
    __syncthreads();
    if (g == 0) {
        float s = ((part[0][j] + part[1][j]) + (part[2][j] + part[3][j])) +
                  ((part[4][j] + part[5][j]) + (part[6][j] + part[7][j]));
        if (b < D) g_Wfused[b * D + j] = s;
        else       g_bias[j] = s + __ldg(&ba[j]);
    }
}

// K3: scatter-add — four edges per warp (proven)
__global__ __launch_bounds__(256) void scatter_kernel(
    const float4* __restrict__ X4,
    const int* __restrict__ src,
    const int* __restrict__ dst, int E) {
    int gt = blockIdx.x * 256 + threadIdx.x;
    int w = gt >> 5;
    int lane = gt & 31;
    int e0 = 4 * w;
    if (e0 >= E) return;
    int m = min(4, E - e0);

    if (m == 4) {
        int4 s = *(const int4*)(src + e0);
        int4 d = *(const int4*)(dst + e0);
        float ns0 = __ldg(&g_ns[s.x]);
        float ns1 = __ldg(&g_ns[s.y]);
        float ns2 = __ldg(&g_ns[s.z]);
        float ns3 = __ldg(&g_ns[s.w]);
        float4 v0 = __ldg(&X4[s.x * 32 + lane]);
        float4 v1 = __ldg(&X4[s.y * 32 + lane]);
        float4 v2 = __ldg(&X4[s.z * 32 + lane]);
        float4 v3 = __ldg(&X4[s.w * 32 + lane]);
        v0.x *= ns0; v0.y *= ns0; v0.z *= ns0; v0.w *= ns0;
        v1.x *= ns1; v1.y *= ns1; v1.z *= ns1; v1.w *= ns1;
        v2.x *= ns2; v2.y *= ns2; v2.z *= ns2; v2.w *= ns2;
        v3.x *= ns3; v3.y *= ns3; v3.z *= ns3; v3.w *= ns3;
        float4* p0 = ((float4*)g_agg) + d.x * 32 + lane;
        float4* p1 = ((float4*)g_agg) + d.y * 32 + lane;
        float4* p2 = ((float4*)g_agg) + d.z * 32 + lane;
        float4* p3 = ((float4*)g_agg) + d.w * 32 + lane;
        asm volatile("red.global.add.v4.f32 [%0], {%1,%2,%3,%4};"
                     :: "l"(p0), "f"(v0.x), "f"(v0.y), "f"(v0.z), "f"(v0.w) : "memory");
        asm volatile("red.global.add.v4.f32 [%0], {%1,%2,%3,%4};"
                     :: "l"(p1), "f"(v1.x), "f"(v1.y), "f"(v1.z), "f"(v1.w) : "memory");
        asm volatile("red.global.add.v4.f32 [%0], {%1,%2,%3,%4};"
                     :: "l"(p2), "f"(v2.x), "f"(v2.y), "f"(v2.z), "f"(v2.w) : "memory");
        asm volatile("red.global.add.v4.f32 [%0], {%1,%2,%3,%4};"
                     :: "l"(p3), "f"(v3.x), "f"(v3.y), "f"(v3.z), "f"(v3.w) : "memory");
    } else {
        for (int e = e0; e < e0 + m; e++) {
            int s = __ldg(&src[e]);
            int d = __ldg(&dst[e]);
            float ns = __ldg(&g_ns[s]);
            float4 v = __ldg(&X4[s * 32 + lane]);
            v.x *= ns; v.y *= ns; v.z *= ns; v.w *= ns;
            float4* p = ((float4*)g_agg) + d * 32 + lane;
            asm volatile("red.global.add.v4.f32 [%0], {%1,%2,%3,%4};"
                         :: "l"(p), "f"(v.x), "f"(v.y), "f"(v.z), "f"(v.w) : "memory");
        }
    }
}

// ---------------------------------------------------------------------------
// K4: tensor-core GEMM: out = (agg*nd) @ W_fused + X @ Wa2 + bias
// 512 threads = 16 warps (4m x 4n), warp tile 32x32, acc 32 regs (r15-proven).
// KC=128: ONE chunk per phase — barrier pairs 8 -> 4, staging MLP 2x, so the
// remaining exposed-latency windows are half as many and better amortized.
// smem 143.4KB (< 228KB; 1 block/SM anyway — regfile-limited).
#define KC 128
#define KPC (KC / 2)         // 64 kpairs per chunk
#define A_STR 72             // == 8 mod 32 -> conflict-free LDS.64 frag reads
#define B_STR 136
#define SA_SZ (128 * A_STR)
#define SB_SZ (KPC * B_STR)
#define SM_U32 (2 * SA_SZ + 2 * SB_SZ)
#define GT 512               // GEMM threads per block

#define MMA_BF16(c, a, b)                                                   \
    asm volatile(                                                           \
        "mma.sync.aligned.m16n8k16.row.col.f32.bf16.bf16.f32 "              \
        "{%0,%1,%2,%3}, {%4,%5,%6,%7}, {%8,%9}, {%0,%1,%2,%3};"             \
        : "+f"((c)[0]), "+f"((c)[1]), "+f"((c)[2]), "+f"((c)[3])            \
        : "r"((a)[0]), "r"((a)[1]), "r"((a)[2]), "r"((a)[3]),               \
          "r"((b)[0]), "r"((b)[1]))

__device__ __forceinline__ void split_pack(float v0, float v1,
                                           unsigned& hi, unsigned& lo) {
    unsigned h;
    asm("cvt.rn.bf16x2.f32 %0, %1, %2;" : "=r"(h) : "f"(v1), "f"(v0));
    float f0 = __uint_as_float(h << 16);
    float f1 = __uint_as_float(h & 0xffff0000u);
    float r0 = v0 - f0;
    float r1 = v1 - f1;
    unsigned l;
    asm("cvt.rn.bf16x2.f32 %0, %1, %2;" : "=r"(l) : "f"(r1), "f"(r0));
    hi = h;
    lo = l;
}

__device__ __forceinline__ int kp_pos(int kp) {
    return (kp & ~7) + ((kp & 3) << 1) + ((kp >> 2) & 1);
}

__global__ __launch_bounds__(GT) void out_gemm_kernel(
    const float* __restrict__ X,
    const float* __restrict__ Wa2,
    float* __restrict__ out, int n) {
    extern __shared__ unsigned sm[];
    unsigned* sAh = sm;
    unsigned* sAl = sm + SA_SZ;
    unsigned* sBh = sm + 2 * SA_SZ;
    unsigned* sBl = sm + 2 * SA_SZ + SB_SZ;

    int tid = threadIdx.x;
    int wid = tid >> 5;        // 0..15
    int lane = tid & 31;
    int gid = lane >> 2;
    int tig = lane & 3;
    int wm = wid >> 2;         // 0..3 -> rows 32*wm
    int wn = wid & 3;          // 0..3 -> cols 32*wn
    int row0 = blockIdx.x * 128;

    float acc[2][4][4];
#pragma unroll
    for (int mt = 0; mt < 2; mt++)
#pragma unroll
        for (int nt = 0; nt < 4; nt++)
#pragma unroll
            for (int i = 0; i < 4; i++) acc[mt][nt][i] = 0.f;

#pragma unroll
    for (int phase = 0; phase < 2; phase++) {
        const float* Asrc = (phase == 0) ? g_agg : X;
        const float* Wsrc = (phase == 0) ? g_Wfused : Wa2;

        // ---- stage A: 128 rows x 128 cols (4096 float4 / 512 thr) -------
#pragma unroll
        for (int it = 0; it < 8; it++) {
            int idx = tid + it * GT;
            int r = idx >> 5;          // row 0..127
            int f4 = idx & 31;         // float4 within full 128-col row
            int grow = row0 + r;
            float4 v = make_float4(0.f, 0.f, 0.f, 0.f);
            if (grow < n) {
                float4* gp = ((float4*)Asrc) + grow * 32 + f4;
                v = *gp;
                if (phase == 0) {
                    float nd = g_nd[grow];
                    v.x *= nd; v.y *= nd; v.z *= nd; v.w *= nd;
                    *gp = make_float4(0.f, 0.f, 0.f, 0.f);  // replay invariant
                }
            }
            unsigned h0, l0, h1, l1;
            split_pack(v.x, v.y, h0, l0);
            split_pack(v.z, v.w, h1, l1);
            int p0 = kp_pos(2 * f4);
            int p1 = kp_pos(2 * f4 + 1);
            int ob = r * A_STR;
            sAh[ob + p0] = h0; sAh[ob + p1] = h1;
            sAl[ob + p0] = l0; sAl[ob + p1] = l1;
        }
        // ---- stage B: 64 kpairs x 32 colgroups (2048 tasks / 512 thr) ----
#pragma unroll
        for (int it = 0; it < 4; it++) {
            int idx = tid + it * GT;
            int kp = idx >> 5;         // 0..63
            int c = idx & 31;
            float4 wa = *(const float4*)&Wsrc[(2 * kp) * D + 4 * c];
            float4 wb = *(const float4*)&Wsrc[(2 * kp + 1) * D + 4 * c];
            unsigned h0, l0, h1, l1, h2, l2, h3, l3;
            split_pack(wa.x, wb.x, h0, l0);
            split_pack(wa.y, wb.y, h1, l1);
            split_pack(wa.z, wb.z, h2, l2);
            split_pack(wa.w, wb.w, h3, l3);
            int o = kp * B_STR + 4 * c;
            *(uint4*)&sBh[o] = make_uint4(h0, h1, h2, h3);
            *(uint4*)&sBl[o] = make_uint4(l0, l1, l2, l3);
        }
        __syncthreads();

        // ---- mma over 8 k16 steps ----------------------------------------
#pragma unroll
        for (int s = 0; s < 8; s++) {
            int kb = s * 8;
            unsigned bh[4][2], bl[4][2];
#pragma unroll
            for (int nt = 0; nt < 4; nt++) {
                int col = wn * 32 + nt * 8 + gid;
                bh[nt][0] = sBh[(kb + tig) * B_STR + col];
                bh[nt][1] = sBh[(kb + tig + 4) * B_STR + col];
                bl[nt][0] = sBl[(kb + tig) * B_STR + col];
                bl[nt][1] = sBl[(kb + tig + 4) * B_STR + col];
            }
#pragma unroll
            for (int mt = 0; mt < 2; mt++) {
                int rb = wm * 32 + mt * 16;
                int oa0 = (rb + gid) * A_STR + kb + 2 * tig;
                int oa1 = (rb + gid + 8) * A_STR + kb + 2 * tig;
                uint2 a02 = *(const uint2*)&sAh[oa0];
                uint2 a13 = *(const uint2*)&sAh[oa1];
                uint2 c02 = *(const uint2*)&sAl[oa0];
                uint2 c13 = *(const uint2*)&sAl[oa1];
                unsigned ah[4] = {a02.x, a13.x, a02.y, a13.y};
                unsigned al[4] = {c02.x, c13.x, c02.y, c13.y};
#pragma unroll
                for (int nt = 0; nt < 4; nt++) {
                    MMA_BF16(acc[mt][nt], ah, bh[nt]);  // hi*hi
                    MMA_BF16(acc[mt][nt], ah, bl[nt]);  // hi*lo
                    MMA_BF16(acc[mt][nt], al, bh[nt]);  // lo*hi
                }
            }
        }
        __syncthreads();
    }

    // ---- epilogue: bias + store ------------------------------------------
#pragma unroll
    for (int mt = 0; mt < 2; mt++) {
        int r = row0 + wm * 32 + mt * 16 + gid;
#pragma unroll
        for (int nt = 0; nt < 4; nt++) {
            int col = wn * 32 + nt * 8 + 2 * tig;
            float2 bv = *(const float2*)&g_bias[col];
            if (r < n) {
                float2 o0 = make_float2(acc[mt][nt][0] + bv.x,
                                        acc[mt][nt][1] + bv.y);
                *(float2*)&out[r * D + col] = o0;
            }
            if (r + 8 < n) {
                float2 o1 = make_float2(acc[mt][nt][2] + bv.x,
                                        acc[mt][nt][3] + bv.y);
                *(float2*)&out[(r + 8) * D + col] = o1;
            }
        }
    }
}

// ---------------------------------------------------------------------------
extern "C" void kernel_launch(void* const* d_in, const int* in_sizes, int n_in,
                              void* d_out, int out_size) {
    const float* features = (const float*)d_in[0];
    const int*   src      = (const int*)d_in[1];
    const int*   dst      = (const int*)d_in[2];
    const float* W_conv   = (const float*)d_in[3];
    const float* b_conv   = (const float*)d_in[4];
    const float* W_aggr   = (const float*)d_in[5];
    const float* b_aggr   = (const float*)d_in[6];
    float* out = (float*)d_out;

    int n = in_sizes[0] / D;
    int E = in_sizes[1];

    cudaFuncSetAttribute(out_gemm_kernel,
                         cudaFuncAttributeMaxDynamicSharedMemorySize,
                         SM_U32 * (int)sizeof(unsigned));

    int dthreads = (E + 3) / 4;
    deg_kernel<<<(dthreads + 255) / 256, 256>>>(src, dst, E);
    int fuse_blocks = (D + 1) + (n + 1023) / 1024;
    fuse_kernel<<<fuse_blocks, 1024>>>(W_conv, W_aggr, b_conv, b_aggr, n);

    long long nwarps = ((long long)E + 3) / 4;
    long long threads = nwarps * 32;
    scatter_kernel<<<(int)((threads + 255) / 256), 256>>>(
        (const float4*)features, src, dst, E);

    out_gemm_kernel<<<(n + 127) / 128, GT, SM_U32 * (int)sizeof(unsigned)>>>(
        features, W_aggr + D * D, out, n);
}

// round 17
// speedup vs baseline: 1.0560x; 1.0560x over previous
#include <cuda_runtime.h>
#include <cuda_bf16.h>
#include <cstdint>

#define N_MAX 50000
#define D 128

// ---- scratch (__device__ globals; no cudaMalloc allowed) -------------------
// Invariant maintained across graph replays: g_agg, g_deg_out, g_deg_in are
// ZERO at kernel_launch entry (module-load init for run 1; each run re-zeros
// them after their last read).
__device__ float g_agg[N_MAX * D];     // scatter accumulator [N,128]
__device__ int   g_deg_out[N_MAX];
__device__ int   g_deg_in[N_MAX];
__device__ float g_ns[N_MAX];          // rsqrt(max(deg_out,1))
__device__ float g_nd[N_MAX];          // rsqrt(max(deg_in,1))
__device__ float g_Wfused[D * D];      // W_conv @ W_aggr[0:128]
__device__ float g_bias[D];            // b_conv @ Wa1 + b_aggr

// ---------------------------------------------------------------------------
// K1: degree histograms — 4 edges per thread via int4
__global__ void deg_kernel(const int* __restrict__ src,
                           const int* __restrict__ dst, int E) {
    int t = blockIdx.x * blockDim.x + threadIdx.x;
    int i = t * 4;
    if (i + 3 < E) {
        int4 s = *(const int4*)(src + i);
        int4 d = *(const int4*)(dst + i);
        atomicAdd(&g_deg_out[s.x], 1);
        atomicAdd(&g_deg_out[s.y], 1);
        atomicAdd(&g_deg_out[s.z], 1);
        atomicAdd(&g_deg_out[s.w], 1);
        atomicAdd(&g_deg_in[d.x], 1);
        atomicAdd(&g_deg_in[d.y], 1);
        atomicAdd(&g_deg_in[d.z], 1);
        atomicAdd(&g_deg_in[d.w], 1);
    } else {
        for (int e = i; e < E; e++) {
            atomicAdd(&g_deg_out[src[e]], 1);
            atomicAdd(&g_deg_in[dst[e]], 1);
        }
    }
}

// K2: fused weight prep + norm factors (+ deg re-zero for next replay).
__global__ __launch_bounds__(1024) void fuse_kernel(
    const float* __restrict__ Wc,
    const float* __restrict__ Wa,
    const float* __restrict__ bc,
    const float* __restrict__ ba, int n) {
    int tid = threadIdx.x;
    int b = blockIdx.x;
    if (b > D) {
        int i = (b - D - 1) * 1024 + tid;
        if (i < n) {
            g_ns[i] = rsqrtf(fmaxf((float)__ldg(&g_deg_out[i]), 1.0f));
            g_nd[i] = rsqrtf(fmaxf((float)__ldg(&g_deg_in[i]), 1.0f));
            g_deg_out[i] = 0;          // restore invariant for next replay
            g_deg_in[i] = 0;
        }
        return;
    }
    __shared__ float wc[D];
    __shared__ float part[8][D];
    int j = tid & 127;
    int g = tid >> 7;          // k-group 0..7
    if (tid < D) wc[tid] = (b < D) ? __ldg(&Wc[b * D + tid]) : __ldg(&bc[tid]);
    __syncthreads();

    int k0 = g * 16;
    float a[8];
#pragma unroll
    for (int i = 0; i < 8; i++) a[i] = 0.f;
#pragma unroll
    for (int kk = 0; kk < 16; kk++)
        a[kk & 7] += wc[k0 + kk] * __ldg(&Wa[(k0 + kk) * D + j]);
    part[g][j] = ((a[0] + a[1]) + (a[2] + a[3])) + ((a[4] + a[5]) + (a[6] + a[7]));
    __syncthreads();
    if (g == 0) {
        float s = ((part[0][j] + part[1][j]) + (part[2][j] + part[3][j])) +
                  ((part[4][j] + part[5][j]) + (part[6][j] + part[7][j]));
        if (b < D) g_Wfused[b * D + j] = s;
        else       g_bias[j] = s + __ldg(&ba[j]);
    }
}

// K3: scatter-add — four edges per warp (proven)
__global__ __launch_bounds__(256) void scatter_kernel(
    const float4* __restrict__ X4,
    const int* __restrict__ src,
    const int* __restrict__ dst, int E) {
    int gt = blockIdx.x * 256 + threadIdx.x;
    int w = gt >> 5;
    int lane = gt & 31;
    int e0 = 4 * w;
    if (e0 >= E) return;
    int m = min(4, E - e0);

    if (m == 4) {
        int4 s = *(const int4*)(src + e0);
        int4 d = *(const int4*)(dst + e0);
        float ns0 = __ldg(&g_ns[s.x]);
        float ns1 = __ldg(&g_ns[s.y]);
        float ns2 = __ldg(&g_ns[s.z]);
        float ns3 = __ldg(&g_ns[s.w]);
        float4 v0 = __ldg(&X4[s.x * 32 + lane]);
        float4 v1 = __ldg(&X4[s.y * 32 + lane]);
        float4 v2 = __ldg(&X4[s.z * 32 + lane]);
        float4 v3 = __ldg(&X4[s.w * 32 + lane]);
        v0.x *= ns0; v0.y *= ns0; v0.z *= ns0; v0.w *= ns0;
        v1.x *= ns1; v1.y *= ns1; v1.z *= ns1; v1.w *= ns1;
        v2.x *= ns2; v2.y *= ns2; v2.z *= ns2; v2.w *= ns2;
        v3.x *= ns3; v3.y *= ns3; v3.z *= ns3; v3.w *= ns3;
        float4* p0 = ((float4*)g_agg) + d.x * 32 + lane;
        float4* p1 = ((float4*)g_agg) + d.y * 32 + lane;
        float4* p2 = ((float4*)g_agg) + d.z * 32 + lane;
        float4* p3 = ((float4*)g_agg) + d.w * 32 + lane;
        asm volatile("red.global.add.v4.f32 [%0], {%1,%2,%3,%4};"
                     :: "l"(p0), "f"(v0.x), "f"(v0.y), "f"(v0.z), "f"(v0.w) : "memory");
        asm volatile("red.global.add.v4.f32 [%0], {%1,%2,%3,%4};"
                     :: "l"(p1), "f"(v1.x), "f"(v1.y), "f"(v1.z), "f"(v1.w) : "memory");
        asm volatile("red.global.add.v4.f32 [%0], {%1,%2,%3,%4};"
                     :: "l"(p2), "f"(v2.x), "f"(v2.y), "f"(v2.z), "f"(v2.w) : "memory");
        asm volatile("red.global.add.v4.f32 [%0], {%1,%2,%3,%4};"
                     :: "l"(p3), "f"(v3.x), "f"(v3.y), "f"(v3.z), "f"(v3.w) : "memory");
    } else {
        for (int e = e0; e < e0 + m; e++) {
            int s = __ldg(&src[e]);
            int d = __ldg(&dst[e]);
            float ns = __ldg(&g_ns[s]);
            float4 v = __ldg(&X4[s * 32 + lane]);
            v.x *= ns; v.y *= ns; v.z *= ns; v.w *= ns;
            float4* p = ((float4*)g_agg) + d * 32 + lane;
            asm volatile("red.global.add.v4.f32 [%0], {%1,%2,%3,%4};"
                         :: "l"(p), "f"(v.x), "f"(v.y), "f"(v.z), "f"(v.w) : "memory");
        }
    }
}

// ---------------------------------------------------------------------------
// K4: tensor-core GEMM: out = (agg*nd) @ W_fused + X @ Wa2 + bias
// r15 layout (512 thr, 16 warps 4x4, warp tile 32x32, KC=64) + SOFTWARE
// PIPELINE: smem double-buffer (2x75.8KB) + register-prefetch of A (+nd) for
// chunk c+1 issued BEFORE the mma loop of chunk c. Barriers 8 -> 4. B loads
// stay at convert time (L2-hot weights). Prefetch adds ~20 regs (target <=128).
#define KC 64
#define KPC (KC / 2)
#define A_STR 40
#define B_STR 136
#define SA_SZ (128 * A_STR)
#define SB_SZ (KPC * B_STR)
#define BUF_U32 (2 * SA_SZ + 2 * SB_SZ)
#define SM_U32 (2 * BUF_U32)
#define GT 512               // GEMM threads per block

#define MMA_BF16(c, a, b)                                                   \
    asm volatile(                                                           \
        "mma.sync.aligned.m16n8k16.row.col.f32.bf16.bf16.f32 "              \
        "{%0,%1,%2,%3}, {%4,%5,%6,%7}, {%8,%9}, {%0,%1,%2,%3};"             \
        : "+f"((c)[0]), "+f"((c)[1]), "+f"((c)[2]), "+f"((c)[3])            \
        : "r"((a)[0]), "r"((a)[1]), "r"((a)[2]), "r"((a)[3]),               \
          "r"((b)[0]), "r"((b)[1]))

__device__ __forceinline__ void split_pack(float v0, float v1,
                                           unsigned& hi, unsigned& lo) {
    unsigned h;
    asm("cvt.rn.bf16x2.f32 %0, %1, %2;" : "=r"(h) : "f"(v1), "f"(v0));
    float f0 = __uint_as_float(h << 16);
    float f1 = __uint_as_float(h & 0xffff0000u);
    float r0 = v0 - f0;
    float r1 = v1 - f1;
    unsigned l;
    asm("cvt.rn.bf16x2.f32 %0, %1, %2;" : "=r"(l) : "f"(r1), "f"(r0));
    hi = h;
    lo = l;
}

__device__ __forceinline__ int kp_pos(int kp) {
    return (kp & ~7) + ((kp & 3) << 1) + ((kp >> 2) & 1);
}

__global__ __launch_bounds__(GT) void out_gemm_kernel(
    const float* __restrict__ X,
    const float* __restrict__ Wa2,
    float* __restrict__ out, int n) {
    extern __shared__ unsigned sm[];

    int tid = threadIdx.x;
    int wid = tid >> 5;        // 0..15
    int lane = tid & 31;
    int gid = lane >> 2;
    int tig = lane & 3;
    int wm = wid >> 2;         // 0..3 -> rows 32*wm
    int wn = wid & 3;          // 0..3 -> cols 32*wn
    int row0 = blockIdx.x * 128;

    float acc[2][4][4];
#pragma unroll
    for (int mt = 0; mt < 2; mt++)
#pragma unroll
        for (int nt = 0; nt < 4; nt++)
#pragma unroll
            for (int i = 0; i < 4; i++) acc[mt][nt][i] = 0.f;

    float4 pa[4];              // A prefetch registers
    float pnd[4];              // nd prefetch

    // chunk c in 0..3: phase = c>>1 (0: agg@Wfused, 1: X@Wa2), ch = c&1
    // ---- prefetch A for chunk c into pa/pnd (zeroing g_agg in phase 0) ----
    auto prefetch_A = [&](int c) {
        int phase = c >> 1, ch = c & 1;
        const float* Asrc = (phase == 0) ? g_agg : X;
#pragma unroll
        for (int it = 0; it < 4; it++) {
            int idx = tid + it * GT;
            int r = idx >> 4;
            int f4 = idx & 15;
            int grow = row0 + r;
            float4 v = make_float4(0.f, 0.f, 0.f, 0.f);
            float nd = 0.f;
            if (grow < n) {
                float4* gp = ((float4*)Asrc) + grow * 32 + ch * 16 + f4;
                v = *gp;
                if (phase == 0) {
                    nd = __ldg(&g_nd[grow]);
                    *gp = make_float4(0.f, 0.f, 0.f, 0.f);  // replay invariant
                } else {
                    nd = 1.f;
                }
            }
            pa[it] = v;
            pnd[it] = nd;
        }
    };
    // ---- convert prefetched A + load/convert B into buffer buf -----------
    auto convert_store = [&](int c, unsigned* buf) {
        unsigned* sAh = buf;
        unsigned* sAl = buf + SA_SZ;
        unsigned* sBh = buf + 2 * SA_SZ;
        unsigned* sBl = buf + 2 * SA_SZ + SB_SZ;
        int phase = c >> 1, ch = c & 1;
        const float* Wsrc = (phase == 0) ? g_Wfused : Wa2;
        int k0 = ch * KC;
#pragma unroll
        for (int it = 0; it < 4; it++) {
            int idx = tid + it * GT;
            int r = idx >> 4;
            int f4 = idx & 15;
            float4 v = pa[it];
            float nd = pnd[it];
            v.x *= nd; v.y *= nd; v.z *= nd; v.w *= nd;
            unsigned h0, l0, h1, l1;
            split_pack(v.x, v.y, h0, l0);
            split_pack(v.z, v.w, h1, l1);
            int p0 = kp_pos(2 * f4);
            int p1 = kp_pos(2 * f4 + 1);
            int ob = r * A_STR;
            sAh[ob + p0] = h0; sAh[ob + p1] = h1;
            sAl[ob + p0] = l0; sAl[ob + p1] = l1;
        }
#pragma unroll
        for (int it = 0; it < 2; it++) {
            int idx = tid + it * GT;
            int kp = idx >> 5;
            int cg = idx & 31;
            float4 wa = *(const float4*)&Wsrc[(k0 + 2 * kp) * D + 4 * cg];
            float4 wb = *(const float4*)&Wsrc[(k0 + 2 * kp + 1) * D + 4 * cg];
            unsigned h0, l0, h1, l1, h2, l2, h3, l3;
            split_pack(wa.x, wb.x, h0, l0);
            split_pack(wa.y, wb.y, h1, l1);
            split_pack(wa.z, wb.z, h2, l2);
            split_pack(wa.w, wb.w, h3, l3);
            int o = kp * B_STR + 4 * cg;
            *(uint4*)&sBh[o] = make_uint4(h0, h1, h2, h3);
            *(uint4*)&sBl[o] = make_uint4(l0, l1, l2, l3);
        }
    };
    // ---- mma on buffer buf ------------------------------------------------
    auto do_mma = [&](unsigned* buf) {
        unsigned* sAh = buf;
        unsigned* sAl = buf + SA_SZ;
        unsigned* sBh = buf + 2 * SA_SZ;
        unsigned* sBl = buf + 2 * SA_SZ + SB_SZ;
#pragma unroll
        for (int s = 0; s < 4; s++) {
            int kb = s * 8;
            unsigned bh[4][2], bl[4][2];
#pragma unroll
            for (int nt = 0; nt < 4; nt++) {
                int col = wn * 32 + nt * 8 + gid;
                bh[nt][0] = sBh[(kb + tig) * B_STR + col];
                bh[nt][1] = sBh[(kb + tig + 4) * B_STR + col];
                bl[nt][0] = sBl[(kb + tig) * B_STR + col];
                bl[nt][1] = sBl[(kb + tig + 4) * B_STR + col];
            }
#pragma unroll
            for (int mt = 0; mt < 2; mt++) {
                int rb = wm * 32 + mt * 16;
                int oa0 = (rb + gid) * A_STR + kb + 2 * tig;
                int oa1 = (rb + gid + 8) * A_STR + kb + 2 * tig;
                uint2 a02 = *(const uint2*)&sAh[oa0];
                uint2 a13 = *(const uint2*)&sAh[oa1];
                uint2 c02 = *(const uint2*)&sAl[oa0];
                uint2 c13 = *(const uint2*)&sAl[oa1];
                unsigned ah[4] = {a02.x, a13.x, a02.y, a13.y};
                unsigned al[4] = {c02.x, c13.x, c02.y, c13.y};
#pragma unroll
                for (int nt = 0; nt < 4; nt++) {
                    MMA_BF16(acc[mt][nt], ah, bh[nt]);  // hi*hi
                    MMA_BF16(acc[mt][nt], ah, bl[nt]);  // hi*lo
                    MMA_BF16(acc[mt][nt], al, bh[nt]);  // lo*hi
                }
            }
        }
    };

    // ---- pipelined mainloop: 4 chunks, double-buffered ---------------------
    prefetch_A(0);
    convert_store(0, sm);
    __syncthreads();
#pragma unroll
    for (int c = 0; c < 4; c++) {
        if (c < 3) prefetch_A(c + 1);           // LDGs in flight under mma
        do_mma(sm + (c & 1) * BUF_U32);
        if (c < 3) {
            convert_store(c + 1, sm + ((c + 1) & 1) * BUF_U32);
            __syncthreads();
        }
    }

    // ---- epilogue: bias + store ------------------------------------------
#pragma unroll
    for (int mt = 0; mt < 2; mt++) {
        int r = row0 + wm * 32 + mt * 16 + gid;
#pragma unroll
        for (int nt = 0; nt < 4; nt++) {
            int col = wn * 32 + nt * 8 + 2 * tig;
            float2 bv = *(const float2*)&g_bias[col];
            if (r < n) {
                float2 o0 = make_float2(acc[mt][nt][0] + bv.x,
                                        acc[mt][nt][1] + bv.y);
                *(float2*)&out[r * D + col] = o0;
            }
            if (r + 8 < n) {
                float2 o1 = make_float2(acc[mt][nt][2] + bv.x,
                                        acc[mt][nt][3] + bv.y);
                *(float2*)&out[(r + 8) * D + col] = o1;
            }
        }
    }
}

// ---------------------------------------------------------------------------
extern "C" void kernel_launch(void* const* d_in, const int* in_sizes, int n_in,
                              void* d_out, int out_size) {
    const float* features = (const float*)d_in[0];
    const int*   src      = (const int*)d_in[1];
    const int*   dst      = (const int*)d_in[2];
    const float* W_conv   = (const float*)d_in[3];
    const float* b_conv   = (const float*)d_in[4];
    const float* W_aggr   = (const float*)d_in[5];
    const float* b_aggr   = (const float*)d_in[6];
    float* out = (float*)d_out;

    int n = in_sizes[0] / D;
    int E = in_sizes[1];

    cudaFuncSetAttribute(out_gemm_kernel,
                         cudaFuncAttributeMaxDynamicSharedMemorySize,
                         SM_U32 * (int)sizeof(unsigned));

    int dthreads = (E + 3) / 4;
    deg_kernel<<<(dthreads + 255) / 256, 256>>>(src, dst, E);
    int fuse_blocks = (D + 1) + (n + 1023) / 1024;
    fuse_kernel<<<fuse_blocks, 1024>>>(W_conv, W_aggr, b_conv, b_aggr, n);

    long long nwarps = ((long long)E + 3) / 4;
    long long threads = nwarps * 32;
    scatter_kernel<<<(int)((threads + 255) / 256), 256>>>(
        (const float4*)features, src, dst, E);

    out_gemm_kernel<<<(n + 127) / 128, GT, SM_U32 * (int)sizeof(unsigned)>>>(
        features, W_aggr + D * D, out, n);
}